// round 2
// baseline (speedup 1.0000x reference)
#include <cuda_runtime.h>
#include <math.h>

#define BB 4
#define NN 8192
#define ROWS (BB*NN)     // 32768
#define CIN 64
#define MID 64
#define COUT 128
#define KNB 16
#define SLICES 8
#define SLEN (NN/SLICES) // 1024
#define EPSBN 1e-5f

// ---------------- scratch ----------------
__device__ float4 g_c4[ROWS];                 // (x,y,z,|c|^2)
__device__ float g_pd[SLICES][ROWS][KNB];     // partial top-k distances (sorted asc)
__device__ int   g_pi[SLICES][ROWS][KNB];     // partial top-k indices
__device__ int   g_knn[ROWS*KNB];
__device__ float g_X [ROWS*CIN];
__device__ float g_Y1[ROWS*MID];
__device__ float g_Ag[ROWS*MID];
__device__ float g_Ya[ROWS*MID];
__device__ float g_Y2[ROWS*COUT];
__device__ float g_Ps1[256*MID],  g_Pq1[256*MID];
__device__ float g_Psa[256*MID],  g_Pqa[256*MID];
__device__ float g_Ps2[256*COUT], g_Pq2[256*COUT];
__device__ float g_A1[MID],  g_C1[MID];
__device__ float g_Aa[MID],  g_Ca[MID];
__device__ float g_A2[COUT], g_C2[COUT];

// ---------------- prep: pack coords into float4 with |c|^2 ----------------
__global__ void __launch_bounds__(256) k_prep(const float* __restrict__ coords)
{
    const int r = blockIdx.x * 256 + threadIdx.x;
    const float x = coords[r*3+0], y = coords[r*3+1], z = coords[r*3+2];
    g_c4[r] = make_float4(x, y, z, x*x + y*y + z*z);
}

// ---------------- kNN partial: each block scans one 1024-candidate slice ----------------
__global__ void __launch_bounds__(256) k_knn()
{
    __shared__ float4 tile[SLEN];   // 16KB
    const int b = blockIdx.y;
    const int s = blockIdx.z;
    const int q = blockIdx.x * 256 + threadIdx.x;
    const float4* cb4 = g_c4 + (size_t)b * NN;

    for (int i = threadIdx.x; i < SLEN; i += 256)
        tile[i] = cb4[s * SLEN + i];

    const float4 qc = cb4[q];
    __syncthreads();

    float bd[KNB];
    int   bi[KNB];
#pragma unroll
    for (int t = 0; t < KNB; ++t) { bd[t] = 3.0e38f; bi[t] = 0; }

#pragma unroll 8
    for (int i = 0; i < SLEN; ++i) {
        const float4 cj = tile[i];
        float dot = qc.x * cj.x;
        dot = fmaf(qc.y, cj.y, dot);
        dot = fmaf(qc.z, cj.z, dot);
        float d = fmaf(-2.0f, dot, qc.w + cj.w);
        if (d < bd[KNB-1]) {
            int j = s * SLEN + i;
#pragma unroll
            for (int t = 0; t < KNB; ++t) {
                if (d < bd[t]) {
                    float td = bd[t]; bd[t] = d; d = td;
                    int   tj = bi[t]; bi[t] = j; j = tj;
                }
            }
        }
    }

    const int row = b * NN + q;
#pragma unroll
    for (int t = 0; t < KNB; ++t) {
        g_pd[s][row][t] = bd[t];
        g_pi[s][row][t] = bi[t];
    }
}

// ---------------- merge 8 sorted partial lists -> global top-16 ----------------
__global__ void __launch_bounds__(256) k_merge()
{
    const int row = blockIdx.x * 256 + threadIdx.x;

    float bd[KNB];
    int   bi[KNB];
#pragma unroll
    for (int t = 0; t < KNB; ++t) { bd[t] = 3.0e38f; bi[t] = 0; }

    for (int s = 0; s < SLICES; ++s) {
        for (int m = 0; m < KNB; ++m) {
            float d = g_pd[s][row][m];
            if (d >= bd[KNB-1]) break;     // partial list sorted asc
            int j = g_pi[s][row][m];
#pragma unroll
            for (int t = 0; t < KNB; ++t) {
                if (d < bd[t]) {
                    float td = bd[t]; bd[t] = d; d = td;
                    int   tj = bi[t]; bi[t] = j; j = tj;
                }
            }
        }
    }

    int* op = g_knn + (size_t)row * KNB;
#pragma unroll
    for (int t = 0; t < KNB; ++t) op[t] = bi[t];
}

// ---------------- gather + mean: one warp per point ----------------
__global__ void __launch_bounds__(256) k_gather(const float* __restrict__ feats)
{
    const int row  = blockIdx.x * 8 + (threadIdx.x >> 5);
    const int lane = threadIdx.x & 31;
    const int b = row >> 13;
    const float* fb = feats + (size_t)b * NN * CIN;
    const int* ip = g_knn + (size_t)row * KNB;

    float2 acc = make_float2(0.f, 0.f);
#pragma unroll
    for (int m = 0; m < KNB; ++m) {
        const int id = ip[m];
        const float2 v = ((const float2*)(fb + (size_t)id * CIN))[lane];
        acc.x += v.x; acc.y += v.y;
    }
    ((float2*)(g_X + (size_t)row * CIN))[lane] =
        make_float2(acc.x * (1.0f/KNB), acc.y * (1.0f/KNB));
}

// ---------------- warp sum ----------------
__device__ __forceinline__ float warp_sum(float v) {
#pragma unroll
    for (int o = 16; o; o >>= 1) v += __shfl_xor_sync(0xffffffffu, v, o);
    return v;
}

// ---------------- MLP1 ----------------
__global__ void __launch_bounds__(128) k_mlp1(const float* __restrict__ W,
                                              const float* __restrict__ bias)
{
    __shared__ float Ws[CIN*MID];
    __shared__ float wsum[4][MID], wsq[4][MID];
    const int tid = threadIdx.x;
    for (int i = tid; i < CIN*MID; i += 128) Ws[i] = W[i];
    __syncthreads();

    const int r = blockIdx.x * 128 + tid;
    float x[CIN];
    {
        const float4* xp = (const float4*)(g_X + (size_t)r * CIN);
#pragma unroll
        for (int i = 0; i < CIN/4; ++i) {
            float4 v = xp[i];
            x[4*i]=v.x; x[4*i+1]=v.y; x[4*i+2]=v.z; x[4*i+3]=v.w;
        }
    }
    const int warp = tid >> 5, lane = tid & 31;
    float4* yp = (float4*)(g_Y1 + (size_t)r * MID);
    const float4* W4 = (const float4*)Ws;
    const float4* b4 = (const float4*)bias;

#pragma unroll
    for (int g = 0; g < MID/4; ++g) {
        float4 acc = b4[g];
#pragma unroll
        for (int k = 0; k < CIN; ++k) {
            const float4 w = W4[k*(MID/4)+g];
            acc.x = fmaf(x[k], w.x, acc.x);
            acc.y = fmaf(x[k], w.y, acc.y);
            acc.z = fmaf(x[k], w.z, acc.z);
            acc.w = fmaf(x[k], w.w, acc.w);
        }
        yp[g] = acc;
        const float vs[4] = {acc.x, acc.y, acc.z, acc.w};
#pragma unroll
        for (int u = 0; u < 4; ++u) {
            const float s = warp_sum(vs[u]);
            const float qq = warp_sum(vs[u]*vs[u]);
            if (lane == 0) { wsum[warp][4*g+u] = s; wsq[warp][4*g+u] = qq; }
        }
    }
    __syncthreads();
    if (tid < MID) {
        g_Ps1[blockIdx.x*MID+tid] = wsum[0][tid]+wsum[1][tid]+wsum[2][tid]+wsum[3][tid];
        g_Pq1[blockIdx.x*MID+tid] = wsq [0][tid]+wsq [1][tid]+wsq [2][tid]+wsq [3][tid];
    }
}

// ---------------- BN stats finalize: parallel group reduction ----------------
// MID channels, 256 partial blocks: 4 groups x 64 partials each.
__device__ __forceinline__ void stats_mid(const float* Ps, const float* Pq,
                                          const float* g, const float* be,
                                          float* A, float* C)
{
    __shared__ float ss[256], sq[256];
    const int tid = threadIdx.x;
    const int c = tid & (MID-1);
    const int grp = tid >> 6;               // 0..3
    float s = 0.f, q = 0.f;
    const int i0 = grp * 64;
#pragma unroll 4
    for (int i = i0; i < i0 + 64; ++i) { s += Ps[i*MID+c]; q += Pq[i*MID+c]; }
    ss[tid] = s; sq[tid] = q;
    __syncthreads();
    if (tid < MID) {
        s = ss[tid] + ss[tid+64] + ss[tid+128] + ss[tid+192];
        q = sq[tid] + sq[tid+64] + sq[tid+128] + sq[tid+192];
        const float m = s / (float)ROWS;
        const float v = q / (float)ROWS - m*m;
        const float a = g[tid] / sqrtf(v + EPSBN);
        A[tid] = a; C[tid] = be[tid] - m*a;
    }
}
__global__ void k_stats1(const float* __restrict__ g, const float* __restrict__ be)
{ stats_mid(g_Ps1, g_Pq1, g, be, g_A1, g_C1); }
__global__ void k_statsa(const float* __restrict__ g, const float* __restrict__ be)
{ stats_mid(g_Psa, g_Pqa, g, be, g_Aa, g_Ca); }

// COUT channels, 256 partials: 512 threads = 4 groups x 64 partials.
__global__ void k_stats2(const float* __restrict__ g, const float* __restrict__ be)
{
    __shared__ float ss[512], sq[512];
    const int tid = threadIdx.x;
    const int c = tid & (COUT-1);
    const int grp = tid >> 7;               // 0..3
    float s = 0.f, q = 0.f;
    const int i0 = grp * 64;
#pragma unroll 4
    for (int i = i0; i < i0 + 64; ++i) { s += g_Ps2[i*COUT+c]; q += g_Pq2[i*COUT+c]; }
    ss[tid] = s; sq[tid] = q;
    __syncthreads();
    if (tid < COUT) {
        s = ss[tid] + ss[tid+128] + ss[tid+256] + ss[tid+384];
        q = sq[tid] + sq[tid+128] + sq[tid+256] + sq[tid+384];
        const float m = s / (float)ROWS;
        const float v = q / (float)ROWS - m*m;
        const float a = g[tid] / sqrtf(v + EPSBN);
        g_A2[tid] = a; g_C2[tid] = be[tid] - m*a;
    }
}

// ---------------- MLPa ----------------
__global__ void __launch_bounds__(128) k_mlpa(const float* __restrict__ W,
                                              const float* __restrict__ bias)
{
    __shared__ float Ws[MID*MID];
    __shared__ float wsum[4][MID], wsq[4][MID];
    const int tid = threadIdx.x;
    for (int i = tid; i < MID*MID; i += 128) Ws[i] = W[i];
    __syncthreads();

    const int r = blockIdx.x * 128 + tid;
    float x[MID];
    {
        const float4* yp = (const float4*)(g_Y1 + (size_t)r * MID);
        float4* ap = (float4*)(g_Ag + (size_t)r * MID);
#pragma unroll
        for (int i = 0; i < MID/4; ++i) {
            float4 v = yp[i];
            float z0 = fmaxf(fmaf(g_A1[4*i+0], v.x, g_C1[4*i+0]), 0.f);
            float z1 = fmaxf(fmaf(g_A1[4*i+1], v.y, g_C1[4*i+1]), 0.f);
            float z2 = fmaxf(fmaf(g_A1[4*i+2], v.z, g_C1[4*i+2]), 0.f);
            float z3 = fmaxf(fmaf(g_A1[4*i+3], v.w, g_C1[4*i+3]), 0.f);
            ap[i] = make_float4(z0, z1, z2, z3);
            x[4*i]=z0; x[4*i+1]=z1; x[4*i+2]=z2; x[4*i+3]=z3;
        }
    }
    const int warp = tid >> 5, lane = tid & 31;
    float4* yp = (float4*)(g_Ya + (size_t)r * MID);
    const float4* W4 = (const float4*)Ws;
    const float4* b4 = (const float4*)bias;

#pragma unroll
    for (int g = 0; g < MID/4; ++g) {
        float4 acc = b4[g];
#pragma unroll
        for (int k = 0; k < MID; ++k) {
            const float4 w = W4[k*(MID/4)+g];
            acc.x = fmaf(x[k], w.x, acc.x);
            acc.y = fmaf(x[k], w.y, acc.y);
            acc.z = fmaf(x[k], w.z, acc.z);
            acc.w = fmaf(x[k], w.w, acc.w);
        }
        yp[g] = acc;
        const float vs[4] = {acc.x, acc.y, acc.z, acc.w};
#pragma unroll
        for (int u = 0; u < 4; ++u) {
            const float s = warp_sum(vs[u]);
            const float qq = warp_sum(vs[u]*vs[u]);
            if (lane == 0) { wsum[warp][4*g+u] = s; wsq[warp][4*g+u] = qq; }
        }
    }
    __syncthreads();
    if (tid < MID) {
        g_Psa[blockIdx.x*MID+tid] = wsum[0][tid]+wsum[1][tid]+wsum[2][tid]+wsum[3][tid];
        g_Pqa[blockIdx.x*MID+tid] = wsq [0][tid]+wsq [1][tid]+wsq [2][tid]+wsq [3][tid];
    }
}

// ---------------- MLP2 ----------------
__global__ void __launch_bounds__(128) k_mlp2(const float* __restrict__ W,
                                              const float* __restrict__ bias)
{
    __shared__ float Ws[MID*COUT];
    __shared__ float wsum[4][COUT], wsq[4][COUT];
    const int tid = threadIdx.x;
    for (int i = tid; i < MID*COUT; i += 128) Ws[i] = W[i];
    __syncthreads();

    const int r = blockIdx.x * 128 + tid;
    float x[MID];
    {
        const float4* yp = (const float4*)(g_Ya + (size_t)r * MID);
        const float4* ap = (const float4*)(g_Ag + (size_t)r * MID);
#pragma unroll
        for (int i = 0; i < MID/4; ++i) {
            float4 y = yp[i];
            float4 a = ap[i];
            float t0 = fmaxf(fmaf(g_Aa[4*i+0], y.x, g_Ca[4*i+0]), 0.f);
            float t1 = fmaxf(fmaf(g_Aa[4*i+1], y.y, g_Ca[4*i+1]), 0.f);
            float t2 = fmaxf(fmaf(g_Aa[4*i+2], y.z, g_Ca[4*i+2]), 0.f);
            float t3 = fmaxf(fmaf(g_Aa[4*i+3], y.w, g_Ca[4*i+3]), 0.f);
            float s0 = 1.0f / (1.0f + expf(-t0));
            float s1 = 1.0f / (1.0f + expf(-t1));
            float s2 = 1.0f / (1.0f + expf(-t2));
            float s3 = 1.0f / (1.0f + expf(-t3));
            x[4*i+0] = fmaf(a.x, s0, a.x);
            x[4*i+1] = fmaf(a.y, s1, a.y);
            x[4*i+2] = fmaf(a.z, s2, a.z);
            x[4*i+3] = fmaf(a.w, s3, a.w);
        }
    }
    const int warp = tid >> 5, lane = tid & 31;
    float4* yp = (float4*)(g_Y2 + (size_t)r * COUT);
    const float4* W4 = (const float4*)Ws;
    const float4* b4 = (const float4*)bias;

#pragma unroll
    for (int g = 0; g < COUT/4; ++g) {
        float4 acc = b4[g];
#pragma unroll
        for (int k = 0; k < MID; ++k) {
            const float4 w = W4[k*(COUT/4)+g];
            acc.x = fmaf(x[k], w.x, acc.x);
            acc.y = fmaf(x[k], w.y, acc.y);
            acc.z = fmaf(x[k], w.z, acc.z);
            acc.w = fmaf(x[k], w.w, acc.w);
        }
        yp[g] = acc;
        const float vs[4] = {acc.x, acc.y, acc.z, acc.w};
#pragma unroll
        for (int u = 0; u < 4; ++u) {
            const float s = warp_sum(vs[u]);
            const float qq = warp_sum(vs[u]*vs[u]);
            if (lane == 0) { wsum[warp][4*g+u] = s; wsq[warp][4*g+u] = qq; }
        }
    }
    __syncthreads();
    if (tid < COUT) {
        g_Ps2[blockIdx.x*COUT+tid] = wsum[0][tid]+wsum[1][tid]+wsum[2][tid]+wsum[3][tid];
        g_Pq2[blockIdx.x*COUT+tid] = wsq [0][tid]+wsq [1][tid]+wsq [2][tid]+wsq [3][tid];
    }
}

// ---------------- final ----------------
__global__ void __launch_bounds__(256) k_final(float* __restrict__ out)
{
    const int i = blockIdx.x * 256 + threadIdx.x;
    const int c = i & (COUT-1);
    out[i] = fmaxf(fmaf(g_A2[c], g_Y2[i], g_C2[c]), 0.f);
}

// ---------------- launch ----------------
extern "C" void kernel_launch(void* const* d_in, const int* in_sizes, int n_in,
                              void* d_out, int out_size)
{
    const float* coords = (const float*)d_in[0];
    const float* feats  = (const float*)d_in[1];
    const float* W1  = (const float*)d_in[3];
    const float* b1  = (const float*)d_in[4];
    const float* g1  = (const float*)d_in[5];
    const float* be1 = (const float*)d_in[6];
    const float* Wa  = (const float*)d_in[7];
    const float* ba  = (const float*)d_in[8];
    const float* ga  = (const float*)d_in[9];
    const float* bea = (const float*)d_in[10];
    const float* W2  = (const float*)d_in[11];
    const float* b2  = (const float*)d_in[12];
    const float* g2  = (const float*)d_in[13];
    const float* be2 = (const float*)d_in[14];
    float* out = (float*)d_out;

    k_prep  <<<ROWS/256, 256>>>(coords);
    k_knn   <<<dim3(NN/256, BB, SLICES), 256>>>();
    k_merge <<<ROWS/256, 256>>>();
    k_gather<<<ROWS/8, 256>>>(feats);
    k_mlp1  <<<256, 128>>>(W1, b1);
    k_stats1<<<1, 256>>>(g1, be1);
    k_mlpa  <<<256, 128>>>(Wa, ba);
    k_statsa<<<1, 256>>>(ga, bea);
    k_mlp2  <<<256, 128>>>(W2, b2);
    k_stats2<<<1, 512>>>(g2, be2);
    k_final <<<(ROWS*COUT)/256, 256>>>(out);
}

// round 3
// speedup vs baseline: 2.2423x; 2.2423x over previous
#include <cuda_runtime.h>
#include <math.h>

#define BB 4
#define NN 8192
#define ROWS (BB*NN)     // 32768
#define CIN 64
#define MID 64
#define COUT 128
#define KNB 16
#define TS 2048
#define EPSBN 1e-5f
#define FULLM 0xffffffffu

// ---------------- scratch ----------------
__device__ float4 g_c4[ROWS];                 // (x,y,z,|c|^2)
__device__ int   g_knn[ROWS*KNB];
__device__ float g_X [ROWS*CIN];
__device__ float g_Y1[ROWS*MID];
__device__ float g_Ag[ROWS*MID];
__device__ float g_Ya[ROWS*MID];
__device__ float g_Y2[ROWS*COUT];
__device__ float g_Ps1[256*MID],  g_Pq1[256*MID];
__device__ float g_Psa[256*MID],  g_Pqa[256*MID];
__device__ float g_Ps2[256*COUT], g_Pq2[256*COUT];
__device__ float g_A1[MID],  g_C1[MID];
__device__ float g_Aa[MID],  g_Ca[MID];
__device__ float g_A2[COUT], g_C2[COUT];

// ---------------- prep: pack coords into float4 with |c|^2 ----------------
__global__ void __launch_bounds__(256) k_prep(const float* __restrict__ coords)
{
    const int r = blockIdx.x * 256 + threadIdx.x;
    const float x = coords[r*3+0], y = coords[r*3+1], z = coords[r*3+2];
    g_c4[r] = make_float4(x, y, z, x*x + y*y + z*z);
}

// ---------------- kNN: one warp per query, distributed sorted top-16 ----------------
// Lane l (l<16) holds the l-th smallest distance so far. Candidates are
// evaluated 32-at-a-time (one per lane); a ballot finds the (rare) passers
// and each is inserted with a convergent warp rotate. Distances use the
// monotonic shift d' = |c|^2 - 2 q.c  (drop |q|^2); selection identical.
__global__ void __launch_bounds__(256) k_knn()
{
    __shared__ float4 tile[TS];   // 32KB
    const int b = blockIdx.y;
    const int warp = threadIdx.x >> 5;
    const int lane = threadIdx.x & 31;
    const int q = blockIdx.x * 8 + warp;
    const float4* cb4 = g_c4 + (size_t)b * NN;

    const float4 qc = cb4[q];
    const float qx = -2.0f*qc.x, qy = -2.0f*qc.y, qz = -2.0f*qc.z;

    float kd = 3.0e38f;     // list value (lanes 0..15), +inf elsewhere
    int   ki = 0;
    float kth = 3.0e38f;    // current 16th-best (lane 15's kd), broadcast

    for (int t0 = 0; t0 < NN; t0 += TS) {
        __syncthreads();
        for (int i = threadIdx.x; i < TS; i += 256)
            tile[i] = cb4[t0 + i];
        __syncthreads();

#pragma unroll 4
        for (int i = lane; i < TS; i += 32) {
            const float4 c = tile[i];
            const float d = fmaf(qx, c.x, fmaf(qy, c.y, fmaf(qz, c.z, c.w)));
            unsigned m = __ballot_sync(FULLM, d < kth);
            while (m) {
                const int src = __ffs(m) - 1; m &= m - 1;
                const float dn = __shfl_sync(FULLM, d, src);
                const int   jn = t0 + __shfl_sync(FULLM, i, src);
                if (dn < kth) {
                    const unsigned le = __ballot_sync(FULLM, kd <= dn) & 0xffffu;
                    const int pos = __popc(le);
                    const float kdp = __shfl_up_sync(FULLM, kd, 1);
                    const int   kip = __shfl_up_sync(FULLM, ki, 1);
                    if (lane == pos)               { kd = dn;  ki = jn;  }
                    else if (lane > pos && lane < KNB) { kd = kdp; ki = kip; }
                    kth = __shfl_sync(FULLM, kd, KNB-1);
                }
            }
        }
    }

    if (lane < KNB)
        g_knn[((size_t)(b*NN + q))*KNB + lane] = ki;
}

// ---------------- gather + mean: one warp per point ----------------
__global__ void __launch_bounds__(256) k_gather(const float* __restrict__ feats)
{
    const int row  = blockIdx.x * 8 + (threadIdx.x >> 5);
    const int lane = threadIdx.x & 31;
    const int b = row >> 13;
    const float* fb = feats + (size_t)b * NN * CIN;
    const int* ip = g_knn + (size_t)row * KNB;

    float2 acc = make_float2(0.f, 0.f);
#pragma unroll
    for (int m = 0; m < KNB; ++m) {
        const int id = ip[m];
        const float2 v = ((const float2*)(fb + (size_t)id * CIN))[lane];
        acc.x += v.x; acc.y += v.y;
    }
    ((float2*)(g_X + (size_t)row * CIN))[lane] =
        make_float2(acc.x * (1.0f/KNB), acc.y * (1.0f/KNB));
}

// ---------------- warp sum ----------------
__device__ __forceinline__ float warp_sum(float v) {
#pragma unroll
    for (int o = 16; o; o >>= 1) v += __shfl_xor_sync(FULLM, v, o);
    return v;
}

// ---------------- MLP1 ----------------
__global__ void __launch_bounds__(128) k_mlp1(const float* __restrict__ W,
                                              const float* __restrict__ bias)
{
    __shared__ float Ws[CIN*MID];
    __shared__ float wsum[4][MID], wsq[4][MID];
    const int tid = threadIdx.x;
    for (int i = tid; i < CIN*MID; i += 128) Ws[i] = W[i];
    __syncthreads();

    const int r = blockIdx.x * 128 + tid;
    float x[CIN];
    {
        const float4* xp = (const float4*)(g_X + (size_t)r * CIN);
#pragma unroll
        for (int i = 0; i < CIN/4; ++i) {
            float4 v = xp[i];
            x[4*i]=v.x; x[4*i+1]=v.y; x[4*i+2]=v.z; x[4*i+3]=v.w;
        }
    }
    const int warp = tid >> 5, lane = tid & 31;
    float4* yp = (float4*)(g_Y1 + (size_t)r * MID);
    const float4* W4 = (const float4*)Ws;
    const float4* b4 = (const float4*)bias;

#pragma unroll
    for (int g = 0; g < MID/4; ++g) {
        float4 acc = b4[g];
#pragma unroll
        for (int k = 0; k < CIN; ++k) {
            const float4 w = W4[k*(MID/4)+g];
            acc.x = fmaf(x[k], w.x, acc.x);
            acc.y = fmaf(x[k], w.y, acc.y);
            acc.z = fmaf(x[k], w.z, acc.z);
            acc.w = fmaf(x[k], w.w, acc.w);
        }
        yp[g] = acc;
        const float vs[4] = {acc.x, acc.y, acc.z, acc.w};
#pragma unroll
        for (int u = 0; u < 4; ++u) {
            const float s = warp_sum(vs[u]);
            const float qq = warp_sum(vs[u]*vs[u]);
            if (lane == 0) { wsum[warp][4*g+u] = s; wsq[warp][4*g+u] = qq; }
        }
    }
    __syncthreads();
    if (tid < MID) {
        g_Ps1[blockIdx.x*MID+tid] = wsum[0][tid]+wsum[1][tid]+wsum[2][tid]+wsum[3][tid];
        g_Pq1[blockIdx.x*MID+tid] = wsq [0][tid]+wsq [1][tid]+wsq [2][tid]+wsq [3][tid];
    }
}

// ---------------- BN stats finalize: parallel group reduction ----------------
__device__ __forceinline__ void stats_mid(const float* Ps, const float* Pq,
                                          const float* g, const float* be,
                                          float* A, float* C)
{
    __shared__ float ss[256], sq[256];
    const int tid = threadIdx.x;
    const int c = tid & (MID-1);
    const int grp = tid >> 6;               // 0..3
    float s = 0.f, q = 0.f;
    const int i0 = grp * 64;
#pragma unroll 4
    for (int i = i0; i < i0 + 64; ++i) { s += Ps[i*MID+c]; q += Pq[i*MID+c]; }
    ss[tid] = s; sq[tid] = q;
    __syncthreads();
    if (tid < MID) {
        s = ss[tid] + ss[tid+64] + ss[tid+128] + ss[tid+192];
        q = sq[tid] + sq[tid+64] + sq[tid+128] + sq[tid+192];
        const float m = s / (float)ROWS;
        const float v = q / (float)ROWS - m*m;
        const float a = g[tid] / sqrtf(v + EPSBN);
        A[tid] = a; C[tid] = be[tid] - m*a;
    }
}
__global__ void k_stats1(const float* __restrict__ g, const float* __restrict__ be)
{ stats_mid(g_Ps1, g_Pq1, g, be, g_A1, g_C1); }
__global__ void k_statsa(const float* __restrict__ g, const float* __restrict__ be)
{ stats_mid(g_Psa, g_Pqa, g, be, g_Aa, g_Ca); }

__global__ void k_stats2(const float* __restrict__ g, const float* __restrict__ be)
{
    __shared__ float ss[512], sq[512];
    const int tid = threadIdx.x;
    const int c = tid & (COUT-1);
    const int grp = tid >> 7;               // 0..3
    float s = 0.f, q = 0.f;
    const int i0 = grp * 64;
#pragma unroll 4
    for (int i = i0; i < i0 + 64; ++i) { s += g_Ps2[i*COUT+c]; q += g_Pq2[i*COUT+c]; }
    ss[tid] = s; sq[tid] = q;
    __syncthreads();
    if (tid < COUT) {
        s = ss[tid] + ss[tid+128] + ss[tid+256] + ss[tid+384];
        q = sq[tid] + sq[tid+128] + sq[tid+256] + sq[tid+384];
        const float m = s / (float)ROWS;
        const float v = q / (float)ROWS - m*m;
        const float a = g[tid] / sqrtf(v + EPSBN);
        g_A2[tid] = a; g_C2[tid] = be[tid] - m*a;
    }
}

// ---------------- MLPa ----------------
__global__ void __launch_bounds__(128) k_mlpa(const float* __restrict__ W,
                                              const float* __restrict__ bias)
{
    __shared__ float Ws[MID*MID];
    __shared__ float wsum[4][MID], wsq[4][MID];
    const int tid = threadIdx.x;
    for (int i = tid; i < MID*MID; i += 128) Ws[i] = W[i];
    __syncthreads();

    const int r = blockIdx.x * 128 + tid;
    float x[MID];
    {
        const float4* yp = (const float4*)(g_Y1 + (size_t)r * MID);
        float4* ap = (float4*)(g_Ag + (size_t)r * MID);
#pragma unroll
        for (int i = 0; i < MID/4; ++i) {
            float4 v = yp[i];
            float z0 = fmaxf(fmaf(g_A1[4*i+0], v.x, g_C1[4*i+0]), 0.f);
            float z1 = fmaxf(fmaf(g_A1[4*i+1], v.y, g_C1[4*i+1]), 0.f);
            float z2 = fmaxf(fmaf(g_A1[4*i+2], v.z, g_C1[4*i+2]), 0.f);
            float z3 = fmaxf(fmaf(g_A1[4*i+3], v.w, g_C1[4*i+3]), 0.f);
            ap[i] = make_float4(z0, z1, z2, z3);
            x[4*i]=z0; x[4*i+1]=z1; x[4*i+2]=z2; x[4*i+3]=z3;
        }
    }
    const int warp = tid >> 5, lane = tid & 31;
    float4* yp = (float4*)(g_Ya + (size_t)r * MID);
    const float4* W4 = (const float4*)Ws;
    const float4* b4 = (const float4*)bias;

#pragma unroll
    for (int g = 0; g < MID/4; ++g) {
        float4 acc = b4[g];
#pragma unroll
        for (int k = 0; k < MID; ++k) {
            const float4 w = W4[k*(MID/4)+g];
            acc.x = fmaf(x[k], w.x, acc.x);
            acc.y = fmaf(x[k], w.y, acc.y);
            acc.z = fmaf(x[k], w.z, acc.z);
            acc.w = fmaf(x[k], w.w, acc.w);
        }
        yp[g] = acc;
        const float vs[4] = {acc.x, acc.y, acc.z, acc.w};
#pragma unroll
        for (int u = 0; u < 4; ++u) {
            const float s = warp_sum(vs[u]);
            const float qq = warp_sum(vs[u]*vs[u]);
            if (lane == 0) { wsum[warp][4*g+u] = s; wsq[warp][4*g+u] = qq; }
        }
    }
    __syncthreads();
    if (tid < MID) {
        g_Psa[blockIdx.x*MID+tid] = wsum[0][tid]+wsum[1][tid]+wsum[2][tid]+wsum[3][tid];
        g_Pqa[blockIdx.x*MID+tid] = wsq [0][tid]+wsq [1][tid]+wsq [2][tid]+wsq [3][tid];
    }
}

// ---------------- MLP2 ----------------
__global__ void __launch_bounds__(128) k_mlp2(const float* __restrict__ W,
                                              const float* __restrict__ bias)
{
    __shared__ float Ws[MID*COUT];
    __shared__ float wsum[4][COUT], wsq[4][COUT];
    const int tid = threadIdx.x;
    for (int i = tid; i < MID*COUT; i += 128) Ws[i] = W[i];
    __syncthreads();

    const int r = blockIdx.x * 128 + tid;
    float x[MID];
    {
        const float4* yp = (const float4*)(g_Ya + (size_t)r * MID);
        const float4* ap = (const float4*)(g_Ag + (size_t)r * MID);
#pragma unroll
        for (int i = 0; i < MID/4; ++i) {
            float4 y = yp[i];
            float4 a = ap[i];
            float t0 = fmaxf(fmaf(g_Aa[4*i+0], y.x, g_Ca[4*i+0]), 0.f);
            float t1 = fmaxf(fmaf(g_Aa[4*i+1], y.y, g_Ca[4*i+1]), 0.f);
            float t2 = fmaxf(fmaf(g_Aa[4*i+2], y.z, g_Ca[4*i+2]), 0.f);
            float t3 = fmaxf(fmaf(g_Aa[4*i+3], y.w, g_Ca[4*i+3]), 0.f);
            float s0 = 1.0f / (1.0f + expf(-t0));
            float s1 = 1.0f / (1.0f + expf(-t1));
            float s2 = 1.0f / (1.0f + expf(-t2));
            float s3 = 1.0f / (1.0f + expf(-t3));
            x[4*i+0] = fmaf(a.x, s0, a.x);
            x[4*i+1] = fmaf(a.y, s1, a.y);
            x[4*i+2] = fmaf(a.z, s2, a.z);
            x[4*i+3] = fmaf(a.w, s3, a.w);
        }
    }
    const int warp = tid >> 5, lane = tid & 31;
    float4* yp = (float4*)(g_Y2 + (size_t)r * COUT);
    const float4* W4 = (const float4*)Ws;
    const float4* b4 = (const float4*)bias;

#pragma unroll
    for (int g = 0; g < COUT/4; ++g) {
        float4 acc = b4[g];
#pragma unroll
        for (int k = 0; k < MID; ++k) {
            const float4 w = W4[k*(COUT/4)+g];
            acc.x = fmaf(x[k], w.x, acc.x);
            acc.y = fmaf(x[k], w.y, acc.y);
            acc.z = fmaf(x[k], w.z, acc.z);
            acc.w = fmaf(x[k], w.w, acc.w);
        }
        yp[g] = acc;
        const float vs[4] = {acc.x, acc.y, acc.z, acc.w};
#pragma unroll
        for (int u = 0; u < 4; ++u) {
            const float s = warp_sum(vs[u]);
            const float qq = warp_sum(vs[u]*vs[u]);
            if (lane == 0) { wsum[warp][4*g+u] = s; wsq[warp][4*g+u] = qq; }
        }
    }
    __syncthreads();
    if (tid < COUT) {
        g_Ps2[blockIdx.x*COUT+tid] = wsum[0][tid]+wsum[1][tid]+wsum[2][tid]+wsum[3][tid];
        g_Pq2[blockIdx.x*COUT+tid] = wsq [0][tid]+wsq [1][tid]+wsq [2][tid]+wsq [3][tid];
    }
}

// ---------------- final ----------------
__global__ void __launch_bounds__(256) k_final(float* __restrict__ out)
{
    const int i = blockIdx.x * 256 + threadIdx.x;
    const int c = i & (COUT-1);
    out[i] = fmaxf(fmaf(g_A2[c], g_Y2[i], g_C2[c]), 0.f);
}

// ---------------- launch ----------------
extern "C" void kernel_launch(void* const* d_in, const int* in_sizes, int n_in,
                              void* d_out, int out_size)
{
    const float* coords = (const float*)d_in[0];
    const float* feats  = (const float*)d_in[1];
    const float* W1  = (const float*)d_in[3];
    const float* b1  = (const float*)d_in[4];
    const float* g1  = (const float*)d_in[5];
    const float* be1 = (const float*)d_in[6];
    const float* Wa  = (const float*)d_in[7];
    const float* ba  = (const float*)d_in[8];
    const float* ga  = (const float*)d_in[9];
    const float* bea = (const float*)d_in[10];
    const float* W2  = (const float*)d_in[11];
    const float* b2  = (const float*)d_in[12];
    const float* g2  = (const float*)d_in[13];
    const float* be2 = (const float*)d_in[14];
    float* out = (float*)d_out;

    k_prep  <<<ROWS/256, 256>>>(coords);
    k_knn   <<<dim3(NN/8, BB), 256>>>();
    k_gather<<<ROWS/8, 256>>>(feats);
    k_mlp1  <<<256, 128>>>(W1, b1);
    k_stats1<<<1, 256>>>(g1, be1);
    k_mlpa  <<<256, 128>>>(Wa, ba);
    k_statsa<<<1, 256>>>(ga, bea);
    k_mlp2  <<<256, 128>>>(W2, b2);
    k_stats2<<<1, 512>>>(g2, be2);
    k_final <<<(ROWS*COUT)/256, 256>>>(out);
}

// round 4
// speedup vs baseline: 2.5950x; 1.1573x over previous
#include <cuda_runtime.h>
#include <math.h>

#define BB 4
#define NN 8192
#define ROWS (BB*NN)     // 32768
#define CIN 64
#define MID 64
#define COUT 128
#define KNB 16
#define TS 2048
#define EPSBN 1e-5f
#define FULLM 0xffffffffu

// ---------------- scratch ----------------
__device__ float4 g_c4[ROWS];                 // (x,y,z,|c|^2)
__device__ int   g_knn[ROWS*KNB];
__device__ float g_X [ROWS*CIN];
__device__ float g_Y1[ROWS*MID];
__device__ float g_Ag[ROWS*MID];
__device__ float g_Ya[ROWS*MID];
__device__ float g_Y2[ROWS*COUT];
__device__ float g_Ps1[256*MID],  g_Pq1[256*MID];
__device__ float g_Psa[256*MID],  g_Pqa[256*MID];
__device__ float g_Ps2[256*COUT], g_Pq2[256*COUT];
__device__ float g_A1[MID],  g_C1[MID];
__device__ float g_Aa[MID],  g_Ca[MID];
__device__ float g_A2[COUT], g_C2[COUT];

// ---------------- prep: pack coords into float4 with |c|^2 (3 chunked launches) ----------------
__global__ void __launch_bounds__(256) k_prep(const float* __restrict__ coords, int off)
{
    const int r = off + blockIdx.x * 256 + threadIdx.x;
    const float x = coords[r*3+0], y = coords[r*3+1], z = coords[r*3+2];
    g_c4[r] = make_float4(x, y, z, x*x + y*y + z*z);
}

// ---------------- kNN: TWO queries per warp ----------------
// List for q0 lives in lanes 0..15 (sorted asc), list for q1 in lanes 16..31.
// Each lane evaluates its candidate against BOTH queries; one ballot per
// 32-candidate group. Inserts are convergent warp rotates gated per half.
__global__ void __launch_bounds__(256) k_knn()
{
    __shared__ float4 tile[TS];   // 32KB
    const int b = blockIdx.y;
    const int warp = threadIdx.x >> 5;
    const int lane = threadIdx.x & 31;
    const float4* cb4 = g_c4 + (size_t)b * NN;

    const int q0 = blockIdx.x * 16 + warp * 2;
    const int q1 = q0 + 1;
    const float4 qa = cb4[q0];
    const float4 qb = cb4[q1];
    const float q0x = -2.0f*qa.x, q0y = -2.0f*qa.y, q0z = -2.0f*qa.z;
    const float q1x = -2.0f*qb.x, q1y = -2.0f*qb.y, q1z = -2.0f*qb.z;

    float kd = 3.0e38f;                 // lane's slot of its half's list
    int   ki = 0;
    float kth0 = 3.0e38f, kth1 = 3.0e38f;

    for (int t0 = 0; t0 < NN; t0 += TS) {
        __syncthreads();
        for (int i = threadIdx.x; i < TS; i += 256)
            tile[i] = cb4[t0 + i];
        __syncthreads();

#pragma unroll 2
        for (int i = lane; i < TS; i += 32) {
            const float4 c = tile[i];
            const float d0 = fmaf(q0x, c.x, fmaf(q0y, c.y, fmaf(q0z, c.z, c.w)));
            const float d1 = fmaf(q1x, c.x, fmaf(q1y, c.y, fmaf(q1z, c.z, c.w)));
            unsigned m = __ballot_sync(FULLM, (d0 < kth0) || (d1 < kth1));
            while (m) {
                const int src = __ffs(m) - 1; m &= m - 1;
                const float dn0 = __shfl_sync(FULLM, d0, src);
                const float dn1 = __shfl_sync(FULLM, d1, src);
                const int   jn  = t0 + __shfl_sync(FULLM, i, src);
                if (dn0 < kth0) {   // warp-uniform branch
                    const unsigned le = __ballot_sync(FULLM, kd <= dn0) & 0xffffu;
                    const int pos = __popc(le);
                    const float kdp = __shfl_up_sync(FULLM, kd, 1);
                    const int   kip = __shfl_up_sync(FULLM, ki, 1);
                    if (lane == pos)                   { kd = dn0; ki = jn; }
                    else if (lane > pos && lane < KNB) { kd = kdp; ki = kip; }
                    kth0 = __shfl_sync(FULLM, kd, 15);
                }
                if (dn1 < kth1) {   // warp-uniform branch
                    const unsigned hi = __ballot_sync(FULLM, kd <= dn1) & 0xffff0000u;
                    const int pos = 16 + __popc(hi);
                    const float kdp = __shfl_up_sync(FULLM, kd, 1);
                    const int   kip = __shfl_up_sync(FULLM, ki, 1);
                    if (lane == pos)      { kd = dn1; ki = jn; }
                    else if (lane > pos)  { kd = kdp; ki = kip; }
                    kth1 = __shfl_sync(FULLM, kd, 31);
                }
            }
        }
    }

    const int qq = q0 + (lane >> 4);
    g_knn[((size_t)(b*NN + qq))*KNB + (lane & 15)] = ki;
}

// ---------------- gather + mean: one warp per point ----------------
__global__ void __launch_bounds__(256) k_gather(const float* __restrict__ feats)
{
    const int row  = blockIdx.x * 8 + (threadIdx.x >> 5);
    const int lane = threadIdx.x & 31;
    const int b = row >> 13;
    const float* fb = feats + (size_t)b * NN * CIN;
    const int* ip = g_knn + (size_t)row * KNB;

    float2 acc = make_float2(0.f, 0.f);
#pragma unroll
    for (int m = 0; m < KNB; ++m) {
        const int id = ip[m];
        const float2 v = ((const float2*)(fb + (size_t)id * CIN))[lane];
        acc.x += v.x; acc.y += v.y;
    }
    ((float2*)(g_X + (size_t)row * CIN))[lane] =
        make_float2(acc.x * (1.0f/KNB), acc.y * (1.0f/KNB));
}

// ---------------- warp sum ----------------
__device__ __forceinline__ float warp_sum(float v) {
#pragma unroll
    for (int o = 16; o; o >>= 1) v += __shfl_xor_sync(FULLM, v, o);
    return v;
}

// ---------------- MLP1: channel-split x4 (16 out channels per block) ----------------
__global__ void __launch_bounds__(128) k_mlp1(const float* __restrict__ W,
                                              const float* __restrict__ bias)
{
    __shared__ float Ws[CIN*16];            // 4KB slice: Ws[k*16+c]
    __shared__ float wsum[4][16], wsq[4][16];
    const int tid = threadIdx.x;
    const int cg = blockIdx.y;              // channel group 0..3
    for (int i = tid; i < CIN*16; i += 128) {
        const int k = i >> 4, c = i & 15;
        Ws[i] = W[k*MID + cg*16 + c];
    }
    __syncthreads();

    const int r = blockIdx.x * 128 + tid;
    float x[CIN];
    {
        const float4* xp = (const float4*)(g_X + (size_t)r * CIN);
#pragma unroll
        for (int i = 0; i < CIN/4; ++i) {
            float4 v = xp[i];
            x[4*i]=v.x; x[4*i+1]=v.y; x[4*i+2]=v.z; x[4*i+3]=v.w;
        }
    }
    const int warp = tid >> 5, lane = tid & 31;
    float4* yp = (float4*)(g_Y1 + (size_t)r * MID + cg*16);
    const float4* W4 = (const float4*)Ws;               // W4[k*4+g]
    const float4* b4 = (const float4*)(bias + cg*16);

#pragma unroll
    for (int g = 0; g < 4; ++g) {
        float4 acc = b4[g];
#pragma unroll
        for (int k = 0; k < CIN; ++k) {
            const float4 w = W4[k*4+g];
            acc.x = fmaf(x[k], w.x, acc.x);
            acc.y = fmaf(x[k], w.y, acc.y);
            acc.z = fmaf(x[k], w.z, acc.z);
            acc.w = fmaf(x[k], w.w, acc.w);
        }
        yp[g] = acc;
        const float vs[4] = {acc.x, acc.y, acc.z, acc.w};
#pragma unroll
        for (int u = 0; u < 4; ++u) {
            const float s = warp_sum(vs[u]);
            const float qq = warp_sum(vs[u]*vs[u]);
            if (lane == 0) { wsum[warp][4*g+u] = s; wsq[warp][4*g+u] = qq; }
        }
    }
    __syncthreads();
    if (tid < 16) {
        g_Ps1[blockIdx.x*MID + cg*16 + tid] = wsum[0][tid]+wsum[1][tid]+wsum[2][tid]+wsum[3][tid];
        g_Pq1[blockIdx.x*MID + cg*16 + tid] = wsq [0][tid]+wsq [1][tid]+wsq [2][tid]+wsq [3][tid];
    }
}

// ---------------- BN stats finalize ----------------
__device__ __forceinline__ void stats_mid(const float* Ps, const float* Pq,
                                          const float* g, const float* be,
                                          float* A, float* C)
{
    __shared__ float ss[256], sq[256];
    const int tid = threadIdx.x;
    const int c = tid & (MID-1);
    const int grp = tid >> 6;
    float s = 0.f, q = 0.f;
    const int i0 = grp * 64;
#pragma unroll 4
    for (int i = i0; i < i0 + 64; ++i) { s += Ps[i*MID+c]; q += Pq[i*MID+c]; }
    ss[tid] = s; sq[tid] = q;
    __syncthreads();
    if (tid < MID) {
        s = ss[tid] + ss[tid+64] + ss[tid+128] + ss[tid+192];
        q = sq[tid] + sq[tid+64] + sq[tid+128] + sq[tid+192];
        const float m = s / (float)ROWS;
        const float v = q / (float)ROWS - m*m;
        const float a = g[tid] / sqrtf(v + EPSBN);
        A[tid] = a; C[tid] = be[tid] - m*a;
    }
}
__global__ void k_stats1(const float* __restrict__ g, const float* __restrict__ be)
{ stats_mid(g_Ps1, g_Pq1, g, be, g_A1, g_C1); }
__global__ void k_statsa(const float* __restrict__ g, const float* __restrict__ be)
{ stats_mid(g_Psa, g_Pqa, g, be, g_Aa, g_Ca); }

__global__ void k_stats2(const float* __restrict__ g, const float* __restrict__ be)
{
    __shared__ float ss[512], sq[512];
    const int tid = threadIdx.x;
    const int c = tid & (COUT-1);
    const int grp = tid >> 7;
    float s = 0.f, q = 0.f;
    const int i0 = grp * 64;
#pragma unroll 4
    for (int i = i0; i < i0 + 64; ++i) { s += g_Ps2[i*COUT+c]; q += g_Pq2[i*COUT+c]; }
    ss[tid] = s; sq[tid] = q;
    __syncthreads();
    if (tid < COUT) {
        s = ss[tid] + ss[tid+128] + ss[tid+256] + ss[tid+384];
        q = sq[tid] + sq[tid+128] + sq[tid+256] + sq[tid+384];
        const float m = s / (float)ROWS;
        const float v = q / (float)ROWS - m*m;
        const float a = g[tid] / sqrtf(v + EPSBN);
        g_A2[tid] = a; g_C2[tid] = be[tid] - m*a;
    }
}

// ---------------- MLPa: channel-split x4 ----------------
__global__ void __launch_bounds__(128) k_mlpa(const float* __restrict__ W,
                                              const float* __restrict__ bias)
{
    __shared__ float Ws[MID*16];
    __shared__ float wsum[4][16], wsq[4][16];
    const int tid = threadIdx.x;
    const int cg = blockIdx.y;
    for (int i = tid; i < MID*16; i += 128) {
        const int k = i >> 4, c = i & 15;
        Ws[i] = W[k*MID + cg*16 + c];
    }
    __syncthreads();

    const int r = blockIdx.x * 128 + tid;
    float x[MID];
    {
        const float4* yp = (const float4*)(g_Y1 + (size_t)r * MID);
        float4* ap = (float4*)(g_Ag + (size_t)r * MID);
#pragma unroll
        for (int i = 0; i < MID/4; ++i) {
            float4 v = yp[i];
            float z0 = fmaxf(fmaf(g_A1[4*i+0], v.x, g_C1[4*i+0]), 0.f);
            float z1 = fmaxf(fmaf(g_A1[4*i+1], v.y, g_C1[4*i+1]), 0.f);
            float z2 = fmaxf(fmaf(g_A1[4*i+2], v.z, g_C1[4*i+2]), 0.f);
            float z3 = fmaxf(fmaf(g_A1[4*i+3], v.w, g_C1[4*i+3]), 0.f);
            if (cg == 0) ap[i] = make_float4(z0, z1, z2, z3);
            x[4*i]=z0; x[4*i+1]=z1; x[4*i+2]=z2; x[4*i+3]=z3;
        }
    }
    const int warp = tid >> 5, lane = tid & 31;
    float4* yp = (float4*)(g_Ya + (size_t)r * MID + cg*16);
    const float4* W4 = (const float4*)Ws;
    const float4* b4 = (const float4*)(bias + cg*16);

#pragma unroll
    for (int g = 0; g < 4; ++g) {
        float4 acc = b4[g];
#pragma unroll
        for (int k = 0; k < MID; ++k) {
            const float4 w = W4[k*4+g];
            acc.x = fmaf(x[k], w.x, acc.x);
            acc.y = fmaf(x[k], w.y, acc.y);
            acc.z = fmaf(x[k], w.z, acc.z);
            acc.w = fmaf(x[k], w.w, acc.w);
        }
        yp[g] = acc;
        const float vs[4] = {acc.x, acc.y, acc.z, acc.w};
#pragma unroll
        for (int u = 0; u < 4; ++u) {
            const float s = warp_sum(vs[u]);
            const float qq = warp_sum(vs[u]*vs[u]);
            if (lane == 0) { wsum[warp][4*g+u] = s; wsq[warp][4*g+u] = qq; }
        }
    }
    __syncthreads();
    if (tid < 16) {
        g_Psa[blockIdx.x*MID + cg*16 + tid] = wsum[0][tid]+wsum[1][tid]+wsum[2][tid]+wsum[3][tid];
        g_Pqa[blockIdx.x*MID + cg*16 + tid] = wsq [0][tid]+wsq [1][tid]+wsq [2][tid]+wsq [3][tid];
    }
}

// ---------------- MLP2: channel-split x4 (32 out channels per block) ----------------
__global__ void __launch_bounds__(128) k_mlp2(const float* __restrict__ W,
                                              const float* __restrict__ bias)
{
    __shared__ float Ws[MID*32];            // 8KB
    __shared__ float wsum[4][32], wsq[4][32];
    const int tid = threadIdx.x;
    const int cg = blockIdx.y;
    for (int i = tid; i < MID*32; i += 128) {
        const int k = i >> 5, c = i & 31;
        Ws[i] = W[k*COUT + cg*32 + c];
    }
    __syncthreads();

    const int r = blockIdx.x * 128 + tid;
    float x[MID];
    {
        const float4* yp = (const float4*)(g_Ya + (size_t)r * MID);
        const float4* ap = (const float4*)(g_Ag + (size_t)r * MID);
#pragma unroll
        for (int i = 0; i < MID/4; ++i) {
            float4 y = yp[i];
            float4 a = ap[i];
            float t0 = fmaxf(fmaf(g_Aa[4*i+0], y.x, g_Ca[4*i+0]), 0.f);
            float t1 = fmaxf(fmaf(g_Aa[4*i+1], y.y, g_Ca[4*i+1]), 0.f);
            float t2 = fmaxf(fmaf(g_Aa[4*i+2], y.z, g_Ca[4*i+2]), 0.f);
            float t3 = fmaxf(fmaf(g_Aa[4*i+3], y.w, g_Ca[4*i+3]), 0.f);
            float s0 = 1.0f / (1.0f + expf(-t0));
            float s1 = 1.0f / (1.0f + expf(-t1));
            float s2 = 1.0f / (1.0f + expf(-t2));
            float s3 = 1.0f / (1.0f + expf(-t3));
            x[4*i+0] = fmaf(a.x, s0, a.x);
            x[4*i+1] = fmaf(a.y, s1, a.y);
            x[4*i+2] = fmaf(a.z, s2, a.z);
            x[4*i+3] = fmaf(a.w, s3, a.w);
        }
    }
    const int warp = tid >> 5, lane = tid & 31;
    float4* yp = (float4*)(g_Y2 + (size_t)r * COUT + cg*32);
    const float4* W4 = (const float4*)Ws;               // W4[k*8+g]
    const float4* b4 = (const float4*)(bias + cg*32);

#pragma unroll
    for (int g = 0; g < 8; ++g) {
        float4 acc = b4[g];
#pragma unroll
        for (int k = 0; k < MID; ++k) {
            const float4 w = W4[k*8+g];
            acc.x = fmaf(x[k], w.x, acc.x);
            acc.y = fmaf(x[k], w.y, acc.y);
            acc.z = fmaf(x[k], w.z, acc.z);
            acc.w = fmaf(x[k], w.w, acc.w);
        }
        yp[g] = acc;
        const float vs[4] = {acc.x, acc.y, acc.z, acc.w};
#pragma unroll
        for (int u = 0; u < 4; ++u) {
            const float s = warp_sum(vs[u]);
            const float qq = warp_sum(vs[u]*vs[u]);
            if (lane == 0) { wsum[warp][4*g+u] = s; wsq[warp][4*g+u] = qq; }
        }
    }
    __syncthreads();
    if (tid < 32) {
        g_Ps2[blockIdx.x*COUT + cg*32 + tid] = wsum[0][tid]+wsum[1][tid]+wsum[2][tid]+wsum[3][tid];
        g_Pq2[blockIdx.x*COUT + cg*32 + tid] = wsq [0][tid]+wsq [1][tid]+wsq [2][tid]+wsq [3][tid];
    }
}

// ---------------- final ----------------
__global__ void __launch_bounds__(256) k_final(float* __restrict__ out)
{
    const int i = blockIdx.x * 256 + threadIdx.x;
    const int c = i & (COUT-1);
    out[i] = fmaxf(fmaf(g_A2[c], g_Y2[i], g_C2[c]), 0.f);
}

// ---------------- launch ----------------
extern "C" void kernel_launch(void* const* d_in, const int* in_sizes, int n_in,
                              void* d_out, int out_size)
{
    const float* coords = (const float*)d_in[0];
    const float* feats  = (const float*)d_in[1];
    const float* W1  = (const float*)d_in[3];
    const float* b1  = (const float*)d_in[4];
    const float* g1  = (const float*)d_in[5];
    const float* be1 = (const float*)d_in[6];
    const float* Wa  = (const float*)d_in[7];
    const float* ba  = (const float*)d_in[8];
    const float* ga  = (const float*)d_in[9];
    const float* bea = (const float*)d_in[10];
    const float* W2  = (const float*)d_in[11];
    const float* b2  = (const float*)d_in[12];
    const float* g2  = (const float*)d_in[13];
    const float* be2 = (const float*)d_in[14];
    float* out = (float*)d_out;

    // prep split into 3 launches so k_knn is launch #4 (ncu shows launch #4)
    k_prep  <<<43, 256>>>(coords, 0);
    k_prep  <<<43, 256>>>(coords, 43*256);
    k_prep  <<<42, 256>>>(coords, 86*256);
    k_knn   <<<dim3(NN/16, BB), 256>>>();
    k_gather<<<ROWS/8, 256>>>(feats);
    k_mlp1  <<<dim3(256, 4), 128>>>(W1, b1);
    k_stats1<<<1, 256>>>(g1, be1);
    k_mlpa  <<<dim3(256, 4), 128>>>(Wa, ba);
    k_statsa<<<1, 256>>>(ga, bea);
    k_mlp2  <<<dim3(256, 4), 128>>>(W2, b2);
    k_stats2<<<1, 512>>>(g2, be2);
    k_final <<<(ROWS*COUT)/256, 256>>>(out);
}